// round 15
// baseline (speedup 1.0000x reference)
#include <cuda_runtime.h>
#include <cstdint>

#define CAP 2097152   // >= BATCH (2,000,000)

// ---------------- device scratch (no allocation allowed) ----------------
__device__ int2 g_list[3][CAP];   // (row, xi) per group
__device__ int  g_counts[3];
__device__ int  g_tile[2];        // work-stealing tile counters (mid, tail)

// packed fp32x2 FMA
__device__ __forceinline__ void ffma2(float2& d, float2 a, float2 b) {
    asm("fma.rn.f32x2 %0, %1, %2, %0;"
        : "+l"(reinterpret_cast<unsigned long long&>(d))
        : "l"(reinterpret_cast<const unsigned long long&>(a)),
          "l"(reinterpret_cast<const unsigned long long&>(b)));
}

// ---------------- kernel 0: reset counters ----------------
__global__ void reset_k() {
    if (threadIdx.x < 3) g_counts[threadIdx.x] = 0;
    if (threadIdx.x < 2) g_tile[threadIdx.x] = 0;
}

// ---------------- kernel 1: compact rows by group (ballot-aggregated) ----------------
__global__ __launch_bounds__(256)
void compact_k(const int* __restrict__ x, const int* __restrict__ grp, int B) {
    __shared__ int s_cnt[3], s_base[3];
    const int tid  = threadIdx.x;
    const int lane = tid & 31;
    for (long long base = (long long)blockIdx.x * 256; base < B;
         base += (long long)gridDim.x * 256) {
        if (tid < 3) s_cnt[tid] = 0;
        __syncthreads();
        const long long row = base + tid;
        int g = -1, xi = 0;
        if (row < B) {
            g  = __ldg(grp + row);
            xi = __ldg(x + row);
        }
        // warp-aggregated ranks: 3 ballots, 3 shared atomics per warp
        int wbase = 0, rank = 0;
        unsigned mymask = 0;
#pragma unroll
        for (int c = 0; c < 3; c++) {
            const unsigned m = __ballot_sync(0xffffffffu, g == c);
            int wb = 0;
            if (lane == 0 && m) wb = atomicAdd(&s_cnt[c], __popc(m));
            wb = __shfl_sync(0xffffffffu, wb, 0);
            if (g == c) { wbase = wb; mymask = m; }
        }
        rank = __popc(mymask & ((1u << lane) - 1u));
        __syncthreads();
        if (tid < 3) s_base[tid] = atomicAdd(&g_counts[tid], s_cnt[tid]);
        __syncthreads();
        if ((unsigned)g < 3u)
            g_list[g][s_base[g] + wbase + rank] = make_int2((int)row, xi);
        __syncthreads();
    }
}

// ---------------- kernel 2: head = pure gather-copy, 2-row unrolled ----------------
__global__ __launch_bounds__(256)
void head_k(const float* __restrict__ head, float* __restrict__ out) {
    const int n      = g_counts[0];
    const int seg    = threadIdx.x & 15;                 // 16 threads x float4 = row
    const int stride = (gridDim.x * 256) >> 4;
    int i = (blockIdx.x * 256 + threadIdx.x) >> 4;
    for (; i + stride < n; i += 2 * stride) {
        const int2 e0 = __ldg(&g_list[0][i]);
        const int2 e1 = __ldg(&g_list[0][i + stride]);
        const float4 v0 = __ldg((const float4*)(head + (size_t)e0.y * 64) + seg);
        const float4 v1 = __ldg((const float4*)(head + (size_t)e1.y * 64) + seg);
        __stcs((float4*)(out + (size_t)e0.x * 64) + seg, v0);
        __stcs((float4*)(out + (size_t)e1.x * 64) + seg, v1);
    }
    if (i < n) {
        const int2 e0 = __ldg(&g_list[0][i]);
        const float4 v0 = __ldg((const float4*)(head + (size_t)e0.y * 64) + seg);
        __stcs((float4*)(out + (size_t)e0.x * 64) + seg, v0);
    }
}

// ---- kernel 3: mid GEMV — K-split S=2, SMEM-staged v, 2-shfl reduce ----
#define MWARPS 8
__global__ __launch_bounds__(256, 2)
void mid_k(const float* __restrict__ mid, const float* __restrict__ Wm,
           const float* __restrict__ bm, float* __restrict__ out) {
    __shared__ float vt[MWARPS][16 * 36];   // stride 36 floats (16B-aligned rows)
    __shared__ int   rb[MWARPS][16];

    const int n    = g_counts[1];
    const int t    = threadIdx.x;
    const int w    = t >> 5;
    const int lane = t & 31;
    const int jg   = lane & 15;
    const int h    = lane >> 4;

    float2 wA[16], wB[16];
#pragma unroll
    for (int q = 0; q < 4; q++)
#pragma unroll
        for (int c = 0; c < 4; c++) {
            const int k = h * 16 + q * 4 + c;
            wA[q * 4 + c] = make_float2(__ldg(Wm + (4 * jg + 0) * 32 + k),
                                        __ldg(Wm + (4 * jg + 1) * 32 + k));
            wB[q * 4 + c] = make_float2(__ldg(Wm + (4 * jg + 2) * 32 + k),
                                        __ldg(Wm + (4 * jg + 3) * 32 + k));
        }
    const float2 b2 = make_float2(__ldg(bm + 4 * jg + 2 * h),
                                  __ldg(bm + 4 * jg + 2 * h + 1));

    const int rl  = lane >> 3;   // gather: 4 rows per LDG.128 instr
    const int seg = lane & 7;    // 8 lanes x float4 cover one 128B row

    for (;;) {
        int tile;
        if (lane == 0) tile = atomicAdd(&g_tile[0], 1);
        tile = __shfl_sync(0xffffffffu, tile, 0);
        const int base = tile * 16;
        if (base >= n) break;
        const int nv = min(16, n - base);

        __syncwarp();   // previous tile fully consumed before overwrite
#pragma unroll
        for (int it = 0; it < 4; it++) {
            const int r = it * 4 + rl;
            const int i = base + min(r, nv - 1);
            const int2 e = __ldg(&g_list[1][i]);      // 8-lane broadcast
            if (seg == 0) rb[w][r] = e.x;
            const float4 v = __ldg((const float4*)(mid + (size_t)e.y * 32) + seg);
            *(float4*)&vt[w][r * 36 + seg * 4] = v;   // coalesced-line gather: 1 wf/row
        }
        __syncwarp();

        for (int r = 0; r < nv; r++) {
            const int orow = rb[w][r];                // LDS broadcast
            const float* vr = &vt[w][r * 36 + h * 16];
            float2 a0 = make_float2(0.f, 0.f), a1 = a0, c0 = a0, c1 = a0;
#pragma unroll
            for (int q = 0; q < 4; q++) {
                const float4 p = *(const float4*)(vr + q * 4);  // dual-addr LDS.128
                ffma2(a0, make_float2(p.x, p.x), wA[q * 4 + 0]);
                ffma2(a1, make_float2(p.y, p.y), wA[q * 4 + 1]);
                ffma2(a0, make_float2(p.z, p.z), wA[q * 4 + 2]);
                ffma2(a1, make_float2(p.w, p.w), wA[q * 4 + 3]);
                ffma2(c0, make_float2(p.x, p.x), wB[q * 4 + 0]);
                ffma2(c1, make_float2(p.y, p.y), wB[q * 4 + 1]);
                ffma2(c0, make_float2(p.z, p.z), wB[q * 4 + 2]);
                ffma2(c1, make_float2(p.w, p.w), wB[q * 4 + 3]);
            }
            const float2 xA = make_float2(a0.x + a1.x, a0.y + a1.y);
            const float2 xB = make_float2(c0.x + c1.x, c0.y + c1.y);
            // 2-shfl cross-half exchange: send what the partner stores
            float2 send = h ? xA : xB;
            send.x = __shfl_xor_sync(0xffffffffu, send.x, 16);
            send.y = __shfl_xor_sync(0xffffffffu, send.y, 16);
            const float2 keep = h ? xB : xA;
            const float2 val = make_float2(keep.x + send.x + b2.x,
                                           keep.y + send.y + b2.y);
            __stcs((float2*)(out + (size_t)orow * 64) + (2 * jg + h), val);
        }
    }
}

// ---- kernel 4: tail GEMV — S=1, SMEM-staged v, broadcast LDS.128 delivery ----
__global__ __launch_bounds__(256, 2)
void tail_k(const float* __restrict__ tail, const float* __restrict__ Wt,
            const float* __restrict__ bt, float* __restrict__ out) {
    __shared__ float vt[MWARPS][16 * 20];   // stride 20 floats (16B-aligned rows)
    __shared__ int   rb[MWARPS][16];

    const int n    = g_counts[2];
    const int t    = threadIdx.x;
    const int w    = t >> 5;
    const int lane = t & 31;

    float2 wk[16];
#pragma unroll
    for (int k = 0; k < 16; k++)
        wk[k] = make_float2(__ldg(Wt + (2 * lane) * 16 + k),
                            __ldg(Wt + (2 * lane + 1) * 16 + k));
    const float2 b2 = make_float2(__ldg(bt + 2 * lane), __ldg(bt + 2 * lane + 1));

    const int rl  = lane >> 2;   // gather: 8 rows per LDG.128 instr
    const int seg = lane & 3;    // 4 lanes x float4 cover one 64B row

    for (;;) {
        int tile;
        if (lane == 0) tile = atomicAdd(&g_tile[1], 1);
        tile = __shfl_sync(0xffffffffu, tile, 0);
        const int base = tile * 16;
        if (base >= n) break;
        const int nv = min(16, n - base);

        __syncwarp();
#pragma unroll
        for (int it = 0; it < 2; it++) {
            const int r = it * 8 + rl;
            const int i = base + min(r, nv - 1);
            const int2 e = __ldg(&g_list[2][i]);      // 4-lane broadcast
            if (seg == 0) rb[w][r] = e.x;
            const float4 v = __ldg((const float4*)(tail + (size_t)e.y * 16) + seg);
            *(float4*)&vt[w][r * 20 + seg * 4] = v;
        }
        __syncwarp();

        for (int r = 0; r < nv; r++) {
            const int orow = rb[w][r];
            const float* vr = &vt[w][r * 20];
            float2 a0 = make_float2(0.f, 0.f), a1 = a0;
#pragma unroll
            for (int q = 0; q < 4; q++) {
                const float4 p = *(const float4*)(vr + q * 4);  // full-broadcast LDS.128
                ffma2(a0, make_float2(p.x, p.x), wk[q * 4 + 0]);
                ffma2(a1, make_float2(p.y, p.y), wk[q * 4 + 1]);
                ffma2(a0, make_float2(p.z, p.z), wk[q * 4 + 2]);
                ffma2(a1, make_float2(p.w, p.w), wk[q * 4 + 3]);
            }
            const float2 val = make_float2(a0.x + a1.x + b2.x, a0.y + a1.y + b2.y);
            __stcs((float2*)(out + (size_t)orow * 64) + lane, val);
        }
    }
}

// ---------------- launcher: fork/join concurrency across streams ----------------
extern "C" void kernel_launch(void* const* d_in, const int* in_sizes, int n_in,
                              void* d_out, int out_size)
{
    // metadata order: x, frequency_groups, head_table, mid_table, tail_table,
    //                 W_mid, b_mid, W_tail, b_tail
    const int*   x    = (const int*)  d_in[0];
    const int*   grp  = (const int*)  d_in[1];
    const float* head = (const float*)d_in[2];
    const float* mid  = (const float*)d_in[3];
    const float* tail = (const float*)d_in[4];
    const float* Wm   = (const float*)d_in[5];
    const float* bm   = (const float*)d_in[6];
    const float* Wt   = (const float*)d_in[7];
    const float* bt   = (const float*)d_in[8];
    float* out = (float*)d_out;

    const int B = in_sizes[0];

    static cudaStream_t s1 = nullptr, s2 = nullptr;
    static cudaEvent_t  ef = nullptr, e1 = nullptr, e2 = nullptr;
    if (s1 == nullptr) {
        cudaStreamCreateWithFlags(&s1, cudaStreamNonBlocking);
        cudaStreamCreateWithFlags(&s2, cudaStreamNonBlocking);
        cudaEventCreateWithFlags(&ef, cudaEventDisableTiming);
        cudaEventCreateWithFlags(&e1, cudaEventDisableTiming);
        cudaEventCreateWithFlags(&e2, cudaEventDisableTiming);
    }

    reset_k  <<<1, 32>>>();
    compact_k<<<2048, 256>>>(x, grp, B);

    // fork: mid and tail run concurrently with head
    cudaEventRecord(ef, 0);
    cudaStreamWaitEvent(s1, ef, 0);
    cudaStreamWaitEvent(s2, ef, 0);

    mid_k <<<888, 256, 0, s1>>>(mid,  Wm, bm, out);
    tail_k<<<888, 256, 0, s2>>>(tail, Wt, bt, out);
    head_k<<<2048, 256>>>(head, out);

    // join back onto the capture stream
    cudaEventRecord(e1, s1);
    cudaEventRecord(e2, s2);
    cudaStreamWaitEvent(0, e1, 0);
    cudaStreamWaitEvent(0, e2, 0);
}

// round 16
// speedup vs baseline: 1.1082x; 1.1082x over previous
#include <cuda_runtime.h>
#include <cstdint>

#define CAP 2097152   // >= BATCH (2,000,000)

// ---------------- device scratch (no allocation allowed) ----------------
__device__ int2 g_list[3][CAP];   // (row, xi) per group
__device__ int  g_counts[3];
__device__ int  g_tile[2];        // work-stealing tile counters (mid, tail)

// packed fp32x2 FMA
__device__ __forceinline__ void ffma2(float2& d, float2 a, float2 b) {
    asm("fma.rn.f32x2 %0, %1, %2, %0;"
        : "+l"(reinterpret_cast<unsigned long long&>(d))
        : "l"(reinterpret_cast<const unsigned long long&>(a)),
          "l"(reinterpret_cast<const unsigned long long&>(b)));
}

// ---------------- kernel 0: reset counters ----------------
__global__ void reset_k() {
    if (threadIdx.x < 3) g_counts[threadIdx.x] = 0;
    if (threadIdx.x < 2) g_tile[threadIdx.x] = 0;
}

// ---------------- kernel 1: compact rows by group (ballot-aggregated) ----------------
__global__ __launch_bounds__(256)
void compact_k(const int* __restrict__ x, const int* __restrict__ grp, int B) {
    __shared__ int s_cnt[3], s_base[3];
    const int tid  = threadIdx.x;
    const int lane = tid & 31;
    for (long long base = (long long)blockIdx.x * 256; base < B;
         base += (long long)gridDim.x * 256) {
        if (tid < 3) s_cnt[tid] = 0;
        __syncthreads();
        const long long row = base + tid;
        int g = -1, xi = 0;
        if (row < B) {
            g  = __ldg(grp + row);
            xi = __ldg(x + row);
        }
        // warp-aggregated ranks: 3 ballots, 3 shared atomics per warp
        int wbase = 0, rank = 0;
        unsigned mymask = 0;
#pragma unroll
        for (int c = 0; c < 3; c++) {
            const unsigned m = __ballot_sync(0xffffffffu, g == c);
            int wb = 0;
            if (lane == 0 && m) wb = atomicAdd(&s_cnt[c], __popc(m));
            wb = __shfl_sync(0xffffffffu, wb, 0);
            if (g == c) { wbase = wb; mymask = m; }
        }
        rank = __popc(mymask & ((1u << lane) - 1u));
        __syncthreads();
        if (tid < 3) s_base[tid] = atomicAdd(&g_counts[tid], s_cnt[tid]);
        __syncthreads();
        if ((unsigned)g < 3u)
            g_list[g][s_base[g] + wbase + rank] = make_int2((int)row, xi);
        __syncthreads();
    }
}

// ---------------- kernel 2: head = pure gather-copy, 2-row unrolled ----------------
__global__ __launch_bounds__(256)
void head_k(const float* __restrict__ head, float* __restrict__ out) {
    const int n      = g_counts[0];
    const int seg    = threadIdx.x & 15;                 // 16 threads x float4 = row
    const int stride = (gridDim.x * 256) >> 4;
    int i = (blockIdx.x * 256 + threadIdx.x) >> 4;
    for (; i + stride < n; i += 2 * stride) {
        const int2 e0 = __ldg(&g_list[0][i]);
        const int2 e1 = __ldg(&g_list[0][i + stride]);
        const float4 v0 = __ldg((const float4*)(head + (size_t)e0.y * 64) + seg);
        const float4 v1 = __ldg((const float4*)(head + (size_t)e1.y * 64) + seg);
        __stcs((float4*)(out + (size_t)e0.x * 64) + seg, v0);
        __stcs((float4*)(out + (size_t)e1.x * 64) + seg, v1);
    }
    if (i < n) {
        const int2 e0 = __ldg(&g_list[0][i]);
        const float4 v0 = __ldg((const float4*)(head + (size_t)e0.y * 64) + seg);
        __stcs((float4*)(out + (size_t)e0.x * 64) + seg, v0);
    }
}

// ---- kernel 3: mid GEMV — K-split S=2, SMEM-staged v, 2-shfl reduce ----
#define MWARPS 8
__global__ __launch_bounds__(256, 2)
void mid_k(const float* __restrict__ mid, const float* __restrict__ Wm,
           const float* __restrict__ bm, float* __restrict__ out) {
    __shared__ float vt[MWARPS][16 * 36];   // stride 36 floats (16B-aligned rows)
    __shared__ int   rb[MWARPS][16];

    const int n    = g_counts[1];
    const int t    = threadIdx.x;
    const int w    = t >> 5;
    const int lane = t & 31;
    const int jg   = lane & 15;
    const int h    = lane >> 4;

    float2 wA[16], wB[16];
#pragma unroll
    for (int q = 0; q < 4; q++)
#pragma unroll
        for (int c = 0; c < 4; c++) {
            const int k = h * 16 + q * 4 + c;
            wA[q * 4 + c] = make_float2(__ldg(Wm + (4 * jg + 0) * 32 + k),
                                        __ldg(Wm + (4 * jg + 1) * 32 + k));
            wB[q * 4 + c] = make_float2(__ldg(Wm + (4 * jg + 2) * 32 + k),
                                        __ldg(Wm + (4 * jg + 3) * 32 + k));
        }
    const float2 b2 = make_float2(__ldg(bm + 4 * jg + 2 * h),
                                  __ldg(bm + 4 * jg + 2 * h + 1));

    const int rl  = lane >> 3;   // gather: 4 rows per LDG.128 instr
    const int seg = lane & 7;    // 8 lanes x float4 cover one 128B row

    for (;;) {
        int tile;
        if (lane == 0) tile = atomicAdd(&g_tile[0], 1);
        tile = __shfl_sync(0xffffffffu, tile, 0);
        const int base = tile * 16;
        if (base >= n) break;
        const int nv = min(16, n - base);

        __syncwarp();   // previous tile fully consumed before overwrite
#pragma unroll
        for (int it = 0; it < 4; it++) {
            const int r = it * 4 + rl;
            const int i = base + min(r, nv - 1);
            const int2 e = __ldg(&g_list[1][i]);      // 8-lane broadcast
            if (seg == 0) rb[w][r] = e.x;
            const float4 v = __ldg((const float4*)(mid + (size_t)e.y * 32) + seg);
            *(float4*)&vt[w][r * 36 + seg * 4] = v;   // coalesced-line gather: 1 wf/row
        }
        __syncwarp();

        for (int r = 0; r < nv; r++) {
            const int orow = rb[w][r];                // LDS broadcast
            const float* vr = &vt[w][r * 36 + h * 16];
            float2 a0 = make_float2(0.f, 0.f), a1 = a0, c0 = a0, c1 = a0;
#pragma unroll
            for (int q = 0; q < 4; q++) {
                const float4 p = *(const float4*)(vr + q * 4);  // dual-addr LDS.128
                ffma2(a0, make_float2(p.x, p.x), wA[q * 4 + 0]);
                ffma2(a1, make_float2(p.y, p.y), wA[q * 4 + 1]);
                ffma2(a0, make_float2(p.z, p.z), wA[q * 4 + 2]);
                ffma2(a1, make_float2(p.w, p.w), wA[q * 4 + 3]);
                ffma2(c0, make_float2(p.x, p.x), wB[q * 4 + 0]);
                ffma2(c1, make_float2(p.y, p.y), wB[q * 4 + 1]);
                ffma2(c0, make_float2(p.z, p.z), wB[q * 4 + 2]);
                ffma2(c1, make_float2(p.w, p.w), wB[q * 4 + 3]);
            }
            const float2 xA = make_float2(a0.x + a1.x, a0.y + a1.y);
            const float2 xB = make_float2(c0.x + c1.x, c0.y + c1.y);
            // 2-shfl cross-half exchange: send what the partner stores
            float2 send = h ? xA : xB;
            send.x = __shfl_xor_sync(0xffffffffu, send.x, 16);
            send.y = __shfl_xor_sync(0xffffffffu, send.y, 16);
            const float2 keep = h ? xB : xA;
            const float2 val = make_float2(keep.x + send.x + b2.x,
                                           keep.y + send.y + b2.y);
            __stcs((float2*)(out + (size_t)orow * 64) + (2 * jg + h), val);
        }
    }
}

// ---- kernel 4: tail GEMV — K-split S=2 (mirrors mid), SMEM-staged v ----
__global__ __launch_bounds__(256, 2)
void tail_k(const float* __restrict__ tail, const float* __restrict__ Wt,
            const float* __restrict__ bt, float* __restrict__ out) {
    __shared__ float vt[MWARPS][16 * 20];   // stride 20 floats (16B-aligned rows)
    __shared__ int   rb[MWARPS][16];

    const int n    = g_counts[2];
    const int t    = threadIdx.x;
    const int w    = t >> 5;
    const int lane = t & 31;
    const int jg   = lane & 15;
    const int h    = lane >> 4;

    // lane (jg,h): outputs j = 4jg..4jg+3 over k-half h (8 of 16 k)
    float2 wA[8], wB[8];
#pragma unroll
    for (int q = 0; q < 2; q++)
#pragma unroll
        for (int c = 0; c < 4; c++) {
            const int k = h * 8 + q * 4 + c;
            wA[q * 4 + c] = make_float2(__ldg(Wt + (4 * jg + 0) * 16 + k),
                                        __ldg(Wt + (4 * jg + 1) * 16 + k));
            wB[q * 4 + c] = make_float2(__ldg(Wt + (4 * jg + 2) * 16 + k),
                                        __ldg(Wt + (4 * jg + 3) * 16 + k));
        }
    const float2 b2 = make_float2(__ldg(bt + 4 * jg + 2 * h),
                                  __ldg(bt + 4 * jg + 2 * h + 1));

    const int rl  = lane >> 2;   // gather: 8 rows per LDG.128 instr
    const int seg = lane & 3;    // 4 lanes x float4 cover one 64B row

    for (;;) {
        int tile;
        if (lane == 0) tile = atomicAdd(&g_tile[1], 1);
        tile = __shfl_sync(0xffffffffu, tile, 0);
        const int base = tile * 16;
        if (base >= n) break;
        const int nv = min(16, n - base);

        __syncwarp();
#pragma unroll
        for (int it = 0; it < 2; it++) {
            const int r = it * 8 + rl;
            const int i = base + min(r, nv - 1);
            const int2 e = __ldg(&g_list[2][i]);      // 4-lane broadcast
            if (seg == 0) rb[w][r] = e.x;
            const float4 v = __ldg((const float4*)(tail + (size_t)e.y * 16) + seg);
            *(float4*)&vt[w][r * 20 + seg * 4] = v;
        }
        __syncwarp();

        for (int r = 0; r < nv; r++) {
            const int orow = rb[w][r];
            const float* vr = &vt[w][r * 20 + h * 8];
            float2 a0 = make_float2(0.f, 0.f), a1 = a0, c0 = a0, c1 = a0;
#pragma unroll
            for (int q = 0; q < 2; q++) {
                const float4 p = *(const float4*)(vr + q * 4);  // dual-addr LDS.128
                ffma2(a0, make_float2(p.x, p.x), wA[q * 4 + 0]);
                ffma2(a1, make_float2(p.y, p.y), wA[q * 4 + 1]);
                ffma2(a0, make_float2(p.z, p.z), wA[q * 4 + 2]);
                ffma2(a1, make_float2(p.w, p.w), wA[q * 4 + 3]);
                ffma2(c0, make_float2(p.x, p.x), wB[q * 4 + 0]);
                ffma2(c1, make_float2(p.y, p.y), wB[q * 4 + 1]);
                ffma2(c0, make_float2(p.z, p.z), wB[q * 4 + 2]);
                ffma2(c1, make_float2(p.w, p.w), wB[q * 4 + 3]);
            }
            const float2 xA = make_float2(a0.x + a1.x, a0.y + a1.y);
            const float2 xB = make_float2(c0.x + c1.x, c0.y + c1.y);
            float2 send = h ? xA : xB;
            send.x = __shfl_xor_sync(0xffffffffu, send.x, 16);
            send.y = __shfl_xor_sync(0xffffffffu, send.y, 16);
            const float2 keep = h ? xB : xA;
            const float2 val = make_float2(keep.x + send.x + b2.x,
                                           keep.y + send.y + b2.y);
            __stcs((float2*)(out + (size_t)orow * 64) + (2 * jg + h), val);
        }
    }
}

// ---------------- launcher: fork/join concurrency across streams ----------------
extern "C" void kernel_launch(void* const* d_in, const int* in_sizes, int n_in,
                              void* d_out, int out_size)
{
    // metadata order: x, frequency_groups, head_table, mid_table, tail_table,
    //                 W_mid, b_mid, W_tail, b_tail
    const int*   x    = (const int*)  d_in[0];
    const int*   grp  = (const int*)  d_in[1];
    const float* head = (const float*)d_in[2];
    const float* mid  = (const float*)d_in[3];
    const float* tail = (const float*)d_in[4];
    const float* Wm   = (const float*)d_in[5];
    const float* bm   = (const float*)d_in[6];
    const float* Wt   = (const float*)d_in[7];
    const float* bt   = (const float*)d_in[8];
    float* out = (float*)d_out;

    const int B = in_sizes[0];

    static cudaStream_t s1 = nullptr, s2 = nullptr;
    static cudaEvent_t  ef = nullptr, e1 = nullptr, e2 = nullptr;
    if (s1 == nullptr) {
        cudaStreamCreateWithFlags(&s1, cudaStreamNonBlocking);
        cudaStreamCreateWithFlags(&s2, cudaStreamNonBlocking);
        cudaEventCreateWithFlags(&ef, cudaEventDisableTiming);
        cudaEventCreateWithFlags(&e1, cudaEventDisableTiming);
        cudaEventCreateWithFlags(&e2, cudaEventDisableTiming);
    }

    reset_k  <<<1, 32>>>();
    compact_k<<<2048, 256>>>(x, grp, B);

    // fork: mid and tail run concurrently with head
    cudaEventRecord(ef, 0);
    cudaStreamWaitEvent(s1, ef, 0);
    cudaStreamWaitEvent(s2, ef, 0);

    mid_k <<<592, 256, 0, s1>>>(mid,  Wm, bm, out);
    tail_k<<<592, 256, 0, s2>>>(tail, Wt, bt, out);
    head_k<<<2048, 256>>>(head, out);

    // join back onto the capture stream
    cudaEventRecord(e1, s1);
    cudaEventRecord(e2, s2);
    cudaStreamWaitEvent(0, e1, 0);
    cudaStreamWaitEvent(0, e2, 0);
}

// round 17
// speedup vs baseline: 1.1524x; 1.0399x over previous
#include <cuda_runtime.h>
#include <cstdint>

#define CAP 2097152   // >= BATCH (2,000,000)

// ---------------- device scratch (no allocation allowed) ----------------
__device__ int2 g_list[3][CAP];   // (row, xi) per group
__device__ int  g_counts[3];
__device__ int  g_tile[2];        // work-stealing tile counters (mid, tail)

// packed fp32x2 FMA
__device__ __forceinline__ void ffma2(float2& d, float2 a, float2 b) {
    asm("fma.rn.f32x2 %0, %1, %2, %0;"
        : "+l"(reinterpret_cast<unsigned long long&>(d))
        : "l"(reinterpret_cast<const unsigned long long&>(a)),
          "l"(reinterpret_cast<const unsigned long long&>(b)));
}

// ---------------- kernel 0: reset counters ----------------
__global__ void reset_k() {
    if (threadIdx.x < 3) g_counts[threadIdx.x] = 0;
    if (threadIdx.x < 2) g_tile[threadIdx.x] = 0;
}

// ---------------- kernel 1: compact rows by group (ballot-aggregated) ----------------
__global__ __launch_bounds__(256)
void compact_k(const int* __restrict__ x, const int* __restrict__ grp, int B) {
    __shared__ int s_cnt[3], s_base[3];
    const int tid  = threadIdx.x;
    const int lane = tid & 31;
    for (long long base = (long long)blockIdx.x * 256; base < B;
         base += (long long)gridDim.x * 256) {
        if (tid < 3) s_cnt[tid] = 0;
        __syncthreads();
        const long long row = base + tid;
        int g = -1, xi = 0;
        if (row < B) {
            g  = __ldg(grp + row);
            xi = __ldg(x + row);
        }
        int wbase = 0, rank = 0;
        unsigned mymask = 0;
#pragma unroll
        for (int c = 0; c < 3; c++) {
            const unsigned m = __ballot_sync(0xffffffffu, g == c);
            int wb = 0;
            if (lane == 0 && m) wb = atomicAdd(&s_cnt[c], __popc(m));
            wb = __shfl_sync(0xffffffffu, wb, 0);
            if (g == c) { wbase = wb; mymask = m; }
        }
        rank = __popc(mymask & ((1u << lane) - 1u));
        __syncthreads();
        if (tid < 3) s_base[tid] = atomicAdd(&g_counts[tid], s_cnt[tid]);
        __syncthreads();
        if ((unsigned)g < 3u)
            g_list[g][s_base[g] + wbase + rank] = make_int2((int)row, xi);
        __syncthreads();
    }
}

// ---------------- kernel 2: head = pure gather-copy, 4-row unrolled MLP ----------------
__global__ __launch_bounds__(256)
void head_k(const float* __restrict__ head, float* __restrict__ out) {
    const int n      = g_counts[0];
    const int seg    = threadIdx.x & 15;                 // 16 threads x float4 = row
    const int stride = (gridDim.x * 256) >> 4;
    int i = (blockIdx.x * 256 + threadIdx.x) >> 4;
    for (; i + 3 * stride < n; i += 4 * stride) {
        const int2 e0 = __ldg(&g_list[0][i]);
        const int2 e1 = __ldg(&g_list[0][i + stride]);
        const int2 e2 = __ldg(&g_list[0][i + 2 * stride]);
        const int2 e3 = __ldg(&g_list[0][i + 3 * stride]);
        const float4 v0 = __ldg((const float4*)(head + (size_t)e0.y * 64) + seg);
        const float4 v1 = __ldg((const float4*)(head + (size_t)e1.y * 64) + seg);
        const float4 v2 = __ldg((const float4*)(head + (size_t)e2.y * 64) + seg);
        const float4 v3 = __ldg((const float4*)(head + (size_t)e3.y * 64) + seg);
        __stcs((float4*)(out + (size_t)e0.x * 64) + seg, v0);
        __stcs((float4*)(out + (size_t)e1.x * 64) + seg, v1);
        __stcs((float4*)(out + (size_t)e2.x * 64) + seg, v2);
        __stcs((float4*)(out + (size_t)e3.x * 64) + seg, v3);
    }
    for (; i < n; i += stride) {
        const int2 e0 = __ldg(&g_list[0][i]);
        const float4 v0 = __ldg((const float4*)(head + (size_t)e0.y * 64) + seg);
        __stcs((float4*)(out + (size_t)e0.x * 64) + seg, v0);
    }
}

// ---- kernel 3: mid GEMV — K-split S=2, SMEM-staged v, 2-shfl reduce ----
#define MWARPS 8
__global__ __launch_bounds__(256, 2)
void mid_k(const float* __restrict__ mid, const float* __restrict__ Wm,
           const float* __restrict__ bm, float* __restrict__ out) {
    __shared__ float vt[MWARPS][16 * 36];   // stride 36 floats (16B-aligned rows)
    __shared__ int   rb[MWARPS][16];

    const int n    = g_counts[1];
    const int t    = threadIdx.x;
    const int w    = t >> 5;
    const int lane = t & 31;
    const int jg   = lane & 15;
    const int h    = lane >> 4;

    float2 wA[16], wB[16];
#pragma unroll
    for (int q = 0; q < 4; q++)
#pragma unroll
        for (int c = 0; c < 4; c++) {
            const int k = h * 16 + q * 4 + c;
            wA[q * 4 + c] = make_float2(__ldg(Wm + (4 * jg + 0) * 32 + k),
                                        __ldg(Wm + (4 * jg + 1) * 32 + k));
            wB[q * 4 + c] = make_float2(__ldg(Wm + (4 * jg + 2) * 32 + k),
                                        __ldg(Wm + (4 * jg + 3) * 32 + k));
        }
    const float2 b2 = make_float2(__ldg(bm + 4 * jg + 2 * h),
                                  __ldg(bm + 4 * jg + 2 * h + 1));

    const int rl  = lane >> 3;   // gather: 4 rows per LDG.128 instr
    const int seg = lane & 7;    // 8 lanes x float4 cover one 128B row

    // one row's consume, shared by fast/slow paths
    auto row_work = [&](int r) {
        const int orow = rb[w][r];
        const float* vr = &vt[w][r * 36 + h * 16];
        float2 a0 = make_float2(0.f, 0.f), a1 = a0, c0 = a0, c1 = a0;
#pragma unroll
        for (int q = 0; q < 4; q++) {
            const float4 p = *(const float4*)(vr + q * 4);  // dual-addr LDS.128
            ffma2(a0, make_float2(p.x, p.x), wA[q * 4 + 0]);
            ffma2(a1, make_float2(p.y, p.y), wA[q * 4 + 1]);
            ffma2(a0, make_float2(p.z, p.z), wA[q * 4 + 2]);
            ffma2(a1, make_float2(p.w, p.w), wA[q * 4 + 3]);
            ffma2(c0, make_float2(p.x, p.x), wB[q * 4 + 0]);
            ffma2(c1, make_float2(p.y, p.y), wB[q * 4 + 1]);
            ffma2(c0, make_float2(p.z, p.z), wB[q * 4 + 2]);
            ffma2(c1, make_float2(p.w, p.w), wB[q * 4 + 3]);
        }
        const float2 xA = make_float2(a0.x + a1.x, a0.y + a1.y);
        const float2 xB = make_float2(c0.x + c1.x, c0.y + c1.y);
        float2 send = h ? xA : xB;
        send.x = __shfl_xor_sync(0xffffffffu, send.x, 16);
        send.y = __shfl_xor_sync(0xffffffffu, send.y, 16);
        const float2 keep = h ? xB : xA;
        const float2 val = make_float2(keep.x + send.x + b2.x,
                                       keep.y + send.y + b2.y);
        __stcs((float2*)(out + (size_t)orow * 64) + (2 * jg + h), val);
    };

    for (;;) {
        int tile;
        if (lane == 0) tile = atomicAdd(&g_tile[0], 1);
        tile = __shfl_sync(0xffffffffu, tile, 0);
        const int base = tile * 16;
        if (base >= n) break;
        const int nv = min(16, n - base);

        __syncwarp();   // previous tile fully consumed before overwrite
#pragma unroll
        for (int it = 0; it < 4; it++) {
            const int r = it * 4 + rl;
            const int i = base + min(r, nv - 1);
            const int2 e = __ldg(&g_list[1][i]);      // 8-lane broadcast
            if (seg == 0) rb[w][r] = e.x;
            const float4 v = __ldg((const float4*)(mid + (size_t)e.y * 32) + seg);
            *(float4*)&vt[w][r * 36 + seg * 4] = v;   // coalesced-line gather: 1 wf/row
        }
        __syncwarp();

        if (nv == 16) {
#pragma unroll 4
            for (int r = 0; r < 16; r++) row_work(r);
        } else {
            for (int r = 0; r < nv; r++) row_work(r);
        }
    }
}

// ---- kernel 4: tail GEMV — K-split S=2 (mirrors mid), SMEM-staged v ----
__global__ __launch_bounds__(256, 3)
void tail_k(const float* __restrict__ tail, const float* __restrict__ Wt,
            const float* __restrict__ bt, float* __restrict__ out) {
    __shared__ float vt[MWARPS][16 * 20];   // stride 20 floats (16B-aligned rows)
    __shared__ int   rb[MWARPS][16];

    const int n    = g_counts[2];
    const int t    = threadIdx.x;
    const int w    = t >> 5;
    const int lane = t & 31;
    const int jg   = lane & 15;
    const int h    = lane >> 4;

    float2 wA[8], wB[8];
#pragma unroll
    for (int q = 0; q < 2; q++)
#pragma unroll
        for (int c = 0; c < 4; c++) {
            const int k = h * 8 + q * 4 + c;
            wA[q * 4 + c] = make_float2(__ldg(Wt + (4 * jg + 0) * 16 + k),
                                        __ldg(Wt + (4 * jg + 1) * 16 + k));
            wB[q * 4 + c] = make_float2(__ldg(Wt + (4 * jg + 2) * 16 + k),
                                        __ldg(Wt + (4 * jg + 3) * 16 + k));
        }
    const float2 b2 = make_float2(__ldg(bt + 4 * jg + 2 * h),
                                  __ldg(bt + 4 * jg + 2 * h + 1));

    const int rl  = lane >> 2;   // gather: 8 rows per LDG.128 instr
    const int seg = lane & 3;    // 4 lanes x float4 cover one 64B row

    auto row_work = [&](int r) {
        const int orow = rb[w][r];
        const float* vr = &vt[w][r * 20 + h * 8];
        float2 a0 = make_float2(0.f, 0.f), a1 = a0, c0 = a0, c1 = a0;
#pragma unroll
        for (int q = 0; q < 2; q++) {
            const float4 p = *(const float4*)(vr + q * 4);  // dual-addr LDS.128
            ffma2(a0, make_float2(p.x, p.x), wA[q * 4 + 0]);
            ffma2(a1, make_float2(p.y, p.y), wA[q * 4 + 1]);
            ffma2(a0, make_float2(p.z, p.z), wA[q * 4 + 2]);
            ffma2(a1, make_float2(p.w, p.w), wA[q * 4 + 3]);
            ffma2(c0, make_float2(p.x, p.x), wB[q * 4 + 0]);
            ffma2(c1, make_float2(p.y, p.y), wB[q * 4 + 1]);
            ffma2(c0, make_float2(p.z, p.z), wB[q * 4 + 2]);
            ffma2(c1, make_float2(p.w, p.w), wB[q * 4 + 3]);
        }
        const float2 xA = make_float2(a0.x + a1.x, a0.y + a1.y);
        const float2 xB = make_float2(c0.x + c1.x, c0.y + c1.y);
        float2 send = h ? xA : xB;
        send.x = __shfl_xor_sync(0xffffffffu, send.x, 16);
        send.y = __shfl_xor_sync(0xffffffffu, send.y, 16);
        const float2 keep = h ? xB : xA;
        const float2 val = make_float2(keep.x + send.x + b2.x,
                                       keep.y + send.y + b2.y);
        __stcs((float2*)(out + (size_t)orow * 64) + (2 * jg + h), val);
    };

    for (;;) {
        int tile;
        if (lane == 0) tile = atomicAdd(&g_tile[1], 1);
        tile = __shfl_sync(0xffffffffu, tile, 0);
        const int base = tile * 16;
        if (base >= n) break;
        const int nv = min(16, n - base);

        __syncwarp();
#pragma unroll
        for (int it = 0; it < 2; it++) {
            const int r = it * 8 + rl;
            const int i = base + min(r, nv - 1);
            const int2 e = __ldg(&g_list[2][i]);      // 4-lane broadcast
            if (seg == 0) rb[w][r] = e.x;
            const float4 v = __ldg((const float4*)(tail + (size_t)e.y * 16) + seg);
            *(float4*)&vt[w][r * 20 + seg * 4] = v;
        }
        __syncwarp();

        if (nv == 16) {
#pragma unroll 4
            for (int r = 0; r < 16; r++) row_work(r);
        } else {
            for (int r = 0; r < nv; r++) row_work(r);
        }
    }
}

// ---------------- launcher: fork/join concurrency across streams ----------------
extern "C" void kernel_launch(void* const* d_in, const int* in_sizes, int n_in,
                              void* d_out, int out_size)
{
    // metadata order: x, frequency_groups, head_table, mid_table, tail_table,
    //                 W_mid, b_mid, W_tail, b_tail
    const int*   x    = (const int*)  d_in[0];
    const int*   grp  = (const int*)  d_in[1];
    const float* head = (const float*)d_in[2];
    const float* mid  = (const float*)d_in[3];
    const float* tail = (const float*)d_in[4];
    const float* Wm   = (const float*)d_in[5];
    const float* bm   = (const float*)d_in[6];
    const float* Wt   = (const float*)d_in[7];
    const float* bt   = (const float*)d_in[8];
    float* out = (float*)d_out;

    const int B = in_sizes[0];

    static cudaStream_t s1 = nullptr, s2 = nullptr;
    static cudaEvent_t  ef = nullptr, e1 = nullptr, e2 = nullptr;
    if (s1 == nullptr) {
        cudaStreamCreateWithFlags(&s1, cudaStreamNonBlocking);
        cudaStreamCreateWithFlags(&s2, cudaStreamNonBlocking);
        cudaEventCreateWithFlags(&ef, cudaEventDisableTiming);
        cudaEventCreateWithFlags(&e1, cudaEventDisableTiming);
        cudaEventCreateWithFlags(&e2, cudaEventDisableTiming);
    }

    reset_k  <<<1, 32>>>();
    compact_k<<<2048, 256>>>(x, grp, B);

    // fork: mid and tail run concurrently with head
    cudaEventRecord(ef, 0);
    cudaStreamWaitEvent(s1, ef, 0);
    cudaStreamWaitEvent(s2, ef, 0);

    mid_k <<<592, 256, 0, s1>>>(mid,  Wm, bm, out);
    tail_k<<<592, 256, 0, s2>>>(tail, Wt, bt, out);
    head_k<<<2048, 256>>>(head, out);

    // join back onto the capture stream
    cudaEventRecord(e1, s1);
    cudaEventRecord(e2, s2);
    cudaStreamWaitEvent(0, e1, 0);
    cudaStreamWaitEvent(0, e2, 0);
}